// round 8
// baseline (speedup 1.0000x reference)
#include <cuda_runtime.h>
#include <math.h>

#define N_BOX 256
#define M_PTS 512
#define KPAIR (M_PTS / 2)        // 256 k-pairs per box
#define KQ    (KPAIR / 4)        // 64 k-pairs per block (k-split 4)
#define NBLK  (N_BOX * 4)        // 1024: boxes x 4 k-quarters

// c2 = log2(e) / (2 * THETA2^2), THETA2 = 400
#define C2  (1.44269504088896340736f / 320000.0f)
#define L2E 1.44269504088896340736f

// Scratch (device globals; no allocations allowed)
__device__ float4 g_XY[N_BOX * KPAIR]; // per (i,k-pair): mx0,mx1,my0,my1
__device__ float4 g_PU[N_BOX * KPAIR]; // per (i,k-pair): P0,P1,u0,u1
__device__ float2 g_V [N_BOX * KPAIR]; // per (i,k-pair): v0,v1
__device__ float4 g_JD[N_BOX * M_PTS]; // per (i,j): Gx,Gy,grad_x,grad_y
__device__ float  g_partials[NBLK];
__device__ unsigned int g_count = 0u;

typedef unsigned long long ull;

__device__ __forceinline__ ull pk(float lo, float hi) {
    ull r; asm("mov.b64 %0, {%1, %2};" : "=l"(r) : "f"(lo), "f"(hi)); return r;
}
__device__ __forceinline__ void upk(float& lo, float& hi, ull v) {
    asm("mov.b64 {%0, %1}, %2;" : "=f"(lo), "=f"(hi) : "l"(v));
}
__device__ __forceinline__ ull fma2(ull a, ull b, ull c) {
    ull d; asm("fma.rn.f32x2 %0, %1, %2, %3;" : "=l"(d) : "l"(a), "l"(b), "l"(c)); return d;
}
__device__ __forceinline__ ull ex2p(ull t) {
    ull e;
    asm("{ .reg .f32 lo, hi, el, eh;\n\t"
        "  mov.b64 {lo, hi}, %1;\n\t"
        "  ex2.approx.f32 el, lo;\n\t"
        "  ex2.approx.f32 eh, hi;\n\t"
        "  mov.b64 %0, {el, eh}; }"
        : "=l"(e) : "l"(t));
    return e;
}
__device__ __forceinline__ float ex2s(float x) {
    float y; asm("ex2.approx.f32 %0, %1;" : "=f"(y) : "f"(x)); return y;
}

// ---------------------------------------------------------------------------
// Prep: one thread per (box i, point m). Identical math to R4/R6 (passing at
// rel_err ~1.2e-6).
// ---------------------------------------------------------------------------
__global__ void __launch_bounds__(512) prep_kernel(
    const float* __restrict__ pred,
    const float* __restrict__ target,
    const float* __restrict__ mask,
    const float* __restrict__ grad_x,
    const float* __restrict__ grad_y,
    const float* __restrict__ offset)
{
    const int i = blockIdx.x;
    const int m = threadIdx.x;
    const int idx = i * M_PTS + m;

    if (i == 0 && m == 0) g_count = 0u;   // reset for this graph replay

    const float off0 = offset[2 * i], off1 = offset[2 * i + 1];
    const float px = pred[5 * i]     - off0;
    const float py = pred[5 * i + 1] - off1;
    const float pw = pred[5 * i + 2];
    const float ph = pred[5 * i + 3];
    const float pa = pred[5 * i + 4];
    const float gx = target[5 * i]     - off0;
    const float gy = target[5 * i + 1] - off1;
    const float gw = target[5 * i + 2];
    const float gh = target[5 * i + 3];
    const float ga = target[5 * i + 4];

    float cga, sga;  sincosf(ga, &sga, &cga);
    float cpa, spa;  sincosf(pa, &spa, &cpa);
    const float inv_gw = 1.0f / gw;
    const float inv_gh = 1.0f / gh;

    const float2 mm = ((const float2*)mask)[idx];
    const float mx = mm.x, my = mm.y;

    const float dx = mx - gx, dy = my - gy;
    const float r2  = dx * dx + dy * dy;
    const float rin = rsqrtf(fmaxf(r2, 1e-30f));
    const float d   = r2 * rin;
    float arg = -dx * rin;                       // cos(acosv)
    arg = fminf(1.0f, fmaxf(-1.0f, arg));
    const float st = fabsf(dy) * rin;            // sin(acosv) = |dy|/d
    const bool  spos = (gy >= my);               // beta = ga + s*acosv
    const float s = spos ? 1.0f : -1.0f;

    const float cb = cga * arg - s * (sga * st); // cos(beta)
    const float sb = sga * arg + s * (cga * st); // sin(beta)

    const float d_w = fabsf(d * cb);
    const float d_h = fabsf(d * sb);

    // (1 - sigmoid(x)) = 1 / (1 + exp(x)), exp via ex2
    const float e1 = ex2s(L2E * 15.0f * (d_w - gw) * inv_gw);
    const float e2 = ex2s(L2E * 15.0f * (d_h - gh) * inv_gh);
    const float a1 = 1.0f / ((1.0f + e1) * (1.0f + e2));

    const float dwp = pw * d_w * inv_gw;
    const float dhp = ph * d_h * inv_gh;
    const float wx =  dwp * cpa, wy = dwp * spa;
    const float hx = -dhp * spa, hy = dhp * cpa;

    // quadrant of beta via arg-space comparisons
    bool q2, q3, q4;
    if (spos) {
        q2 = (ga <= 0.0f) && (arg >= cga);
        q3 = false;
        q4 = (arg < sga) && ((ga <= 0.0f) || (arg >= -cga));
    } else {
        q2 = (arg > -sga) && ((ga <= 0.0f) || (arg <= cga));
        q3 = (arg <= -sga) && ((ga >= 0.0f) || (arg > -cga));
        q4 = false;
    }

    float gpx, gpy;
    if (q2)      { gpx =  wx - hx;  gpy =  wy - hy; }
    else if (q3) { gpx =  wx + hx;  gpy =  wy + hy; }
    else if (q4) { gpx = -wx + hx;  gpy = -wy + hy; }
    else         { gpx = -wx - hx;  gpy = -wy - hy; }

    const float gxv = grad_x[idx];
    const float gyv = grad_y[idx];

    const int k2 = idx >> 1;
    const int o  = m & 1;
    ((float*)&g_XY[k2])[o]     = mx;
    ((float*)&g_XY[k2])[2 + o] = my;
    ((float*)&g_PU[k2])[o]     = C2 * (mx * mx + my * my);   // P (Q folded out)
    ((float*)&g_PU[k2])[2 + o] = a1 * gxv;
    ((float*)&g_V [k2])[o]     = a1 * gyv;

    g_JD[idx] = make_float4(px + gpx, py + gpy, gxv, gyv);
}

// ---------------------------------------------------------------------------
// Main: 1024 blocks x 128 threads; block = (box i, k-quarter).
// Each thread owns FOUR j's (tid + {0,128,256,384}) and loops over 64
// k-pairs: one set of k-loads feeds all 4 j's -> 8 independent exp chains
// per thread for deep ILP. Epilogue reloads jd (Gx,Gy,gx,gy) from global so
// only na/nb/accums are loop-live (fits the 73-reg cap of (128,7)).
// ---------------------------------------------------------------------------
__global__ void __launch_bounds__(128, 7) main_kernel(float* __restrict__ out)
{
    __shared__ __align__(16) ull sK[KQ * 6];   // 48B per k-pair, interleaved
    __shared__ float sWarp[4];
    __shared__ int   sLast;

    const int b   = blockIdx.x;
    const int i   = b >> 2;
    const int kc  = b & 3;
    const int tid = threadIdx.x;
    const int kbase = i * KPAIR + kc * KQ;

    // stage interleaved: pairs 0..63 by threads 0..63
    if (tid < KQ) {
        const float4 xy = g_XY[kbase + tid];
        const float4 pu = g_PU[kbase + tid];
        const float2 v  = g_V [kbase + tid];
        ull* dst = &sK[tid * 6];
        ((float4*)dst)[0] = xy;
        ((float4*)dst)[1] = pu;
        ((float2*)dst)[4] = v;
    }

    // four j's per thread: coefficient setup (before sync; independent)
    ull na[4], nb[4];
#pragma unroll
    for (int h = 0; h < 4; ++h) {
        const float4 jd = g_JD[i * M_PTS + tid + h * 128];
        const float naf = -2.0f * C2 * jd.x;
        const float nbf = -2.0f * C2 * jd.y;
        na[h] = pk(naf, naf);
        nb[h] = pk(nbf, nbf);
    }
    __syncthreads();

    ull A[4] = {0, 0, 0, 0}, B[4] = {0, 0, 0, 0};
    const ull* p = sK;

#pragma unroll 2
    for (int k2 = 0; k2 < KQ; ++k2, p += 6) {
        const ulonglong2 xy = *(const ulonglong2*)(p);      // (mx0,mx1),(my0,my1)
        const ulonglong2 pu = *(const ulonglong2*)(p + 2);  // (P0,P1),(u0,u1)
        const ull        v2 = p[4];                         // (v0,v1)

#pragma unroll
        for (int h = 0; h < 4; ++h) {
            ull t = fma2(na[h], xy.x, pu.x);
            t = fma2(nb[h], xy.y, t);
            const ull e = ex2p(t);
            A[h] = fma2(e, pu.y, A[h]);
            B[h] = fma2(e, v2,   B[h]);
        }
    }

    // epilogue: reload jd per j (L2-resident), apply weights and 2^Q
    float partial = 0.0f;
#pragma unroll
    for (int h = 0; h < 4; ++h) {
        const float4 jd = __ldg(&g_JD[i * M_PTS + tid + h * 128]);
        const float twoQ = ex2s(C2 * (jd.x * jd.x + jd.y * jd.y));
        float al, ah, bl, bh;
        upk(al, ah, A[h]); upk(bl, bh, B[h]);
        partial += (jd.z * (al + ah) + jd.w * (bl + bh)) * twoQ;
    }

    // deterministic block reduction (4 warps)
#pragma unroll
    for (int o = 16; o > 0; o >>= 1)
        partial += __shfl_down_sync(0xffffffffu, partial, o);
    if ((tid & 31) == 0) sWarp[tid >> 5] = partial;
    __syncthreads();

    if (tid == 0) {
        g_partials[b] = sWarp[0] + sWarp[1] + sWarp[2] + sWarp[3];
        __threadfence();
        unsigned int old = atomicAdd(&g_count, 1u);
        sLast = (old == NBLK - 1) ? 1 : 0;
    }
    __syncthreads();

    // last block: fixed-order final reduction (deterministic)
    if (sLast) {
        float s = 0.0f;
#pragma unroll
        for (int r = 0; r < NBLK / 128; ++r)
            s += __ldcg(&g_partials[tid + r * 128]);
#pragma unroll
        for (int o = 16; o > 0; o >>= 1)
            s += __shfl_down_sync(0xffffffffu, s, o);
        if ((tid & 31) == 0) sWarp[tid >> 5] = s;
        __syncthreads();
        if (tid == 0) {
            float v = sWarp[0] + sWarp[1] + sWarp[2] + sWarp[3];
            const double scale = 1.0 / ((double)N_BOX * (double)M_PTS * (double)M_PTS *
                                        2.0 * 3.14159265358979323846 * 400.0);
            *out = (float)((double)v * scale);
        }
    }
}

// ---------------------------------------------------------------------------
extern "C" void kernel_launch(void* const* d_in, const int* in_sizes, int n_in,
                              void* d_out, int out_size)
{
    const float* pred    = (const float*)d_in[0];
    const float* target  = (const float*)d_in[1];
    const float* mask    = (const float*)d_in[2];
    const float* grad_x  = (const float*)d_in[3];
    const float* grad_y  = (const float*)d_in[4];
    const float* offset  = (const float*)d_in[5];
    float* out = (float*)d_out;

    prep_kernel<<<N_BOX, 512>>>(pred, target, mask, grad_x, grad_y, offset);
    main_kernel<<<NBLK, 128>>>(out);
}

// round 9
// speedup vs baseline: 1.0713x; 1.0713x over previous
#include <cuda_runtime.h>
#include <math.h>

#define N_BOX 256
#define M_PTS 512
#define KHALF 128                 // k-pairs per block (256 m-points)
#define NBLK  (N_BOX * 2 * 2)     // 1024: boxes x 2 j-halves x 2 k-halves

// c2 = log2(e) / (2 * THETA2^2), THETA2 = 400
#define C2  (1.44269504088896340736f / 320000.0f)
#define L2E 1.44269504088896340736f

__device__ float g_partials[NBLK];
__device__ unsigned int g_count = 0u;   // reset by last block each run

typedef unsigned long long ull;

__device__ __forceinline__ ull pk(float lo, float hi) {
    ull r; asm("mov.b64 %0, {%1, %2};" : "=l"(r) : "f"(lo), "f"(hi)); return r;
}
__device__ __forceinline__ void upk(float& lo, float& hi, ull v) {
    asm("mov.b64 {%0, %1}, %2;" : "=f"(lo), "=f"(hi) : "l"(v));
}
__device__ __forceinline__ float ex2s(float x) {
    float y; asm("ex2.approx.f32 %0, %1;" : "=f"(y) : "f"(x)); return y;
}

struct PrepOut {
    float mx, my, P, u, v;   // k-side
    float Gx, Gy, gx, gy;    // j-side
};

// ---------------------------------------------------------------------------
// Fully fused kernel. Block = (box i, j-half, k-half); 128 threads.
// Phase 1 (inline prep): each thread preps 2 m-points for its k-side smem
// slot and 2 m-points for its own j's (registers). Phase 2: R6-style core
// (2 j's/thread over 128 k-pairs, f32x2 packed, fused asm). Phase 3:
// deterministic block + grid reduction via atomic completion counter.
// ---------------------------------------------------------------------------
__global__ void __launch_bounds__(128, 7) fused_kernel(
    const float* __restrict__ pred,
    const float* __restrict__ target,
    const float* __restrict__ mask,
    const float* __restrict__ grad_x,
    const float* __restrict__ grad_y,
    const float* __restrict__ offset,
    float* __restrict__ out)
{
    __shared__ __align__(16) ull sK[KHALF * 6];  // 48B per k-pair, interleaved
    __shared__ float sWarp[4];
    __shared__ int   sLast;

    const int b   = blockIdx.x;
    const int i   = b >> 2;
    const int jc  = (b >> 1) & 1;
    const int kc  = b & 1;
    const int tid = threadIdx.x;

    // ---- per-box scalars (uniform within block; broadcast loads) ----
    const float off0 = offset[2 * i], off1 = offset[2 * i + 1];
    const float px = pred[5 * i]     - off0;
    const float py = pred[5 * i + 1] - off1;
    const float pw = pred[5 * i + 2];
    const float ph = pred[5 * i + 3];
    const float pa = pred[5 * i + 4];
    const float gxc = target[5 * i]     - off0;
    const float gyc = target[5 * i + 1] - off1;
    const float gw  = target[5 * i + 2];
    const float gh  = target[5 * i + 3];
    const float ga  = target[5 * i + 4];

    float cga, sga;  sincosf(ga, &sga, &cga);
    float cpa, spa;  sincosf(pa, &spa, &cpa);
    const float inv_gw = 1.0f / gw;
    const float inv_gh = 1.0f / gh;

    // ---- inline prep for one m-point ----
    auto prep = [&](int m) -> PrepOut {
        const int idx = i * M_PTS + m;
        const float2 mm = ((const float2*)mask)[idx];
        const float mx = mm.x, my = mm.y;

        const float dx = mx - gxc, dy = my - gyc;
        const float r2  = dx * dx + dy * dy;
        const float rin = rsqrtf(fmaxf(r2, 1e-30f));
        const float d   = r2 * rin;
        float arg = -dx * rin;                       // cos(acosv)
        arg = fminf(1.0f, fmaxf(-1.0f, arg));
        const float st = fabsf(dy) * rin;            // sin(acosv)
        const bool  spos = (gyc >= my);              // beta = ga + s*acosv
        const float s = spos ? 1.0f : -1.0f;

        const float cb = cga * arg - s * (sga * st); // cos(beta)
        const float sb = sga * arg + s * (cga * st); // sin(beta)

        const float d_w = fabsf(d * cb);
        const float d_h = fabsf(d * sb);

        const float e1 = ex2s(L2E * 15.0f * (d_w - gw) * inv_gw);
        const float e2 = ex2s(L2E * 15.0f * (d_h - gh) * inv_gh);
        const float a1 = 1.0f / ((1.0f + e1) * (1.0f + e2));

        const float dwp = pw * d_w * inv_gw;
        const float dhp = ph * d_h * inv_gh;
        const float wx =  dwp * cpa, wy = dwp * spa;
        const float hx = -dhp * spa, hy = dhp * cpa;

        bool q2, q3, q4;
        if (spos) {
            q2 = (ga <= 0.0f) && (arg >= cga);
            q3 = false;
            q4 = (arg < sga) && ((ga <= 0.0f) || (arg >= -cga));
        } else {
            q2 = (arg > -sga) && ((ga <= 0.0f) || (arg <= cga));
            q3 = (arg <= -sga) && ((ga >= 0.0f) || (arg > -cga));
            q4 = false;
        }

        float gpx, gpy;
        if (q2)      { gpx =  wx - hx;  gpy =  wy - hy; }
        else if (q3) { gpx =  wx + hx;  gpy =  wy + hy; }
        else if (q4) { gpx = -wx + hx;  gpy = -wy + hy; }
        else         { gpx = -wx - hx;  gpy = -wy - hy; }

        const float gxv = grad_x[idx];
        const float gyv = grad_y[idx];

        PrepOut o;
        o.mx = mx; o.my = my;
        o.P  = C2 * (mx * mx + my * my);
        o.u  = a1 * gxv;
        o.v  = a1 * gyv;
        o.Gx = px + gpx; o.Gy = py + gpy;
        o.gx = gxv; o.gy = gyv;
        return o;
    };

    // ---- phase 1a: k-side (pair slot tid, m = kc*256 + 2tid, +1) ----
    {
        const int m0 = kc * 256 + 2 * tid;
        const PrepOut k0 = prep(m0);
        const PrepOut k1 = prep(m0 + 1);
        ull* dst = &sK[tid * 6];
        ((float4*)dst)[0] = make_float4(k0.mx, k1.mx, k0.my, k1.my);
        ((float4*)dst)[1] = make_float4(k0.P,  k1.P,  k0.u,  k1.u);
        ((float2*)dst)[4] = make_float2(k0.v,  k1.v);
    }

    // ---- phase 1b: j-side (own j's: jc*256 + tid, +128) ----
    const PrepOut J0 = prep(jc * 256 + tid);
    const PrepOut J1 = prep(jc * 256 + tid + 128);
    __syncthreads();

    const ull na0 = pk(-2.0f * C2 * J0.Gx, -2.0f * C2 * J0.Gx);
    const ull nb0 = pk(-2.0f * C2 * J0.Gy, -2.0f * C2 * J0.Gy);
    const ull na1 = pk(-2.0f * C2 * J1.Gx, -2.0f * C2 * J1.Gx);
    const ull nb1 = pk(-2.0f * C2 * J1.Gy, -2.0f * C2 * J1.Gy);
    const float twoQ0 = ex2s(C2 * (J0.Gx * J0.Gx + J0.Gy * J0.Gy));
    const float twoQ1 = ex2s(C2 * (J1.Gx * J1.Gx + J1.Gy * J1.Gy));

    // ---- phase 2: core loop (R6 shape) ----
    ull A0 = 0, B0 = 0, A1 = 0, B1 = 0;
    const ull* p = sK;

#pragma unroll 4
    for (int k2 = 0; k2 < KHALF; ++k2, p += 6) {
        ulonglong2 xy = *(const ulonglong2*)(p);      // (mx0,mx1),(my0,my1)
        ulonglong2 pu = *(const ulonglong2*)(p + 2);  // (P0,P1),(u0,u1)
        ull        v2 = p[4];                         // (v0,v1)

        asm volatile(
            "{\n\t"
            ".reg .f32 tl, th, el, eh;\n\t"
            ".reg .b64 t, e;\n\t"
            // j0
            "fma.rn.f32x2 t, %4, %8, %10;\n\t"
            "fma.rn.f32x2 t, %5, %9, t;\n\t"
            "mov.b64 {tl, th}, t;\n\t"
            "ex2.approx.f32 el, tl;\n\t"
            "ex2.approx.f32 eh, th;\n\t"
            "mov.b64 e, {el, eh};\n\t"
            "fma.rn.f32x2 %0, e, %11, %0;\n\t"
            "fma.rn.f32x2 %1, e, %12, %1;\n\t"
            // j1
            "fma.rn.f32x2 t, %6, %8, %10;\n\t"
            "fma.rn.f32x2 t, %7, %9, t;\n\t"
            "mov.b64 {tl, th}, t;\n\t"
            "ex2.approx.f32 el, tl;\n\t"
            "ex2.approx.f32 eh, th;\n\t"
            "mov.b64 e, {el, eh};\n\t"
            "fma.rn.f32x2 %2, e, %11, %2;\n\t"
            "fma.rn.f32x2 %3, e, %12, %3;\n\t"
            "}"
            : "+l"(A0), "+l"(B0), "+l"(A1), "+l"(B1)
            : "l"(na0), "l"(nb0), "l"(na1), "l"(nb1),
              "l"(xy.x), "l"(xy.y), "l"(pu.x), "l"(pu.y), "l"(v2));
    }

    float al, ah, bl, bh;
    upk(al, ah, A0); upk(bl, bh, B0);
    float partial = (J0.gx * (al + ah) + J0.gy * (bl + bh)) * twoQ0;
    upk(al, ah, A1); upk(bl, bh, B1);
    partial += (J1.gx * (al + ah) + J1.gy * (bl + bh)) * twoQ1;

    // ---- phase 3: deterministic block reduction (4 warps) ----
#pragma unroll
    for (int o = 16; o > 0; o >>= 1)
        partial += __shfl_down_sync(0xffffffffu, partial, o);
    if ((tid & 31) == 0) sWarp[tid >> 5] = partial;
    __syncthreads();

    if (tid == 0) {
        g_partials[b] = sWarp[0] + sWarp[1] + sWarp[2] + sWarp[3];
        __threadfence();
        unsigned int old = atomicAdd(&g_count, 1u);
        sLast = (old == NBLK - 1) ? 1 : 0;
    }
    __syncthreads();

    // last block: fixed-order final reduction (deterministic regardless of
    // which block executes it), then reset the counter for the next replay.
    if (sLast) {
        float s = 0.0f;
#pragma unroll
        for (int r = 0; r < NBLK / 128; ++r)
            s += __ldcg(&g_partials[tid + r * 128]);
#pragma unroll
        for (int o = 16; o > 0; o >>= 1)
            s += __shfl_down_sync(0xffffffffu, s, o);
        if ((tid & 31) == 0) sWarp[tid >> 5] = s;
        __syncthreads();
        if (tid == 0) {
            float v = sWarp[0] + sWarp[1] + sWarp[2] + sWarp[3];
            const double scale = 1.0 / ((double)N_BOX * (double)M_PTS * (double)M_PTS *
                                        2.0 * 3.14159265358979323846 * 400.0);
            *out = (float)((double)v * scale);
            g_count = 0u;   // ready for next graph replay
        }
    }
}

// ---------------------------------------------------------------------------
extern "C" void kernel_launch(void* const* d_in, const int* in_sizes, int n_in,
                              void* d_out, int out_size)
{
    const float* pred    = (const float*)d_in[0];
    const float* target  = (const float*)d_in[1];
    const float* mask    = (const float*)d_in[2];
    const float* grad_x  = (const float*)d_in[3];
    const float* grad_y  = (const float*)d_in[4];
    const float* offset  = (const float*)d_in[5];
    float* out = (float*)d_out;

    fused_kernel<<<NBLK, 128>>>(pred, target, mask, grad_x, grad_y, offset, out);
}